// round 11
// baseline (speedup 1.0000x reference)
#include <cuda_runtime.h>
#include <cuda_fp16.h>
#include <cstdint>

#define B_    8
#define CIN   320
#define COUT  320
#define H_    64
#define W_    64
#define NPIX  32768     // B*H*W
#define KTOT  2880      // k = tap*320 + ci (tap-major)
#define BM    320
#define BN    128
#define BK    64        // 4 mma k16 steps; tap constant per stage
#define NKI   45
#define NTH   640       // 20 warps: 10 m-pos x 2 n-pos, warp tile 32x64
#define NSTG  3

// __device__ scratch
__device__ __align__(16) __half g_xh[(size_t)NPIX * CIN];      // NHWC fp16 acts (21MB)
__device__ __align__(16) __half g_wh[(size_t)COUT * KTOT];     // weights [o][tap][ci]

// ---------------- helpers ----------------
__device__ __forceinline__ void cp_async16_cg(uint32_t dst, const void* src, int nbytes) {
    asm volatile("cp.async.cg.shared.global [%0], [%1], 16, %2;\n"
                 :: "r"(dst), "l"(src), "r"(nbytes));
}
__device__ __forceinline__ void cp_async16_ca(uint32_t dst, const void* src, int nbytes) {
    asm volatile("cp.async.ca.shared.global [%0], [%1], 16, %2;\n"
                 :: "r"(dst), "l"(src), "r"(nbytes));
}
__device__ __forceinline__ void ldsm_x4(uint32_t* r, uint32_t addr) {
    asm volatile("ldmatrix.sync.aligned.m8n8.x4.shared.b16 {%0,%1,%2,%3}, [%4];"
                 : "=r"(r[0]), "=r"(r[1]), "=r"(r[2]), "=r"(r[3]) : "r"(addr));
}
__device__ __forceinline__ void hmma(float* d, const uint32_t* a, uint32_t b0, uint32_t b1) {
    asm volatile("mma.sync.aligned.m16n8k16.row.col.f32.f16.f16.f32 "
                 "{%0,%1,%2,%3}, {%4,%5,%6,%7}, {%8,%9}, {%0,%1,%2,%3};"
                 : "+f"(d[0]), "+f"(d[1]), "+f"(d[2]), "+f"(d[3])
                 : "r"(a[0]), "r"(a[1]), "r"(a[2]), "r"(a[3]), "r"(b0), "r"(b1));
}
__device__ __forceinline__ uint32_t swz(uint32_t row, uint32_t byte_in_row) {
    return row * 128 + (byte_in_row ^ ((row & 7) << 4));
}

// ---------------- Fused prep: quantize->NHWC (blocks 0..1023) + weight reorder ------
// quant blocks: grid.x in [0,1024): bh = blk>>1, ci-half = blk&1 (160 ci each)
// weight blocks: grid.x in [1024,1344): o = blk - 1024
#define QSTR 165   // 32-bit words per w-row in smem (odd -> conflict-free)
__global__ void prep_kernel(const float* __restrict__ x,
                            const int* __restrict__ wint,
                            const float* __restrict__ inv_p,
                            const float* __restrict__ zp_p)
{
    __shared__ uint32_t t32[64 * QSTR];   // 42240B? no: 64*165*4 = 42240 ... (fits)
    const int tid = threadIdx.x;          // 0..255

    if (blockIdx.x >= 1024) {
        // ---- weight reorder: one o per block ----
        const int o = blockIdx.x - 1024;
        const int* src = wint + (size_t)o * 2880;
        __half* dst = g_wh + (size_t)o * KTOT;
        #pragma unroll
        for (int i = 0; i < 12; i++) {
            int j = tid + i * 256;         // dst index: tap*320 + ci
            if (j < 2880) {
                int tap = j / 320;
                int ci  = j - tap * 320;
                dst[j] = __int2half_rn(src[ci * 9 + tap]);
            }
        }
        return;
    }

    // ---- quantize: (b,h) row, one 160-ci half ----
    const float inv = inv_p[0];
    const float zp  = zp_p[0];
    const int bh   = blockIdx.x >> 1;
    const int half = blockIdx.x & 1;
    const int b    = bh >> 6, h = bh & 63;
    const int ci_base = half * 160;

    const int w  = tid & 63;
    const int cq = tid >> 6;               // 0..3
    const float* xb = x + (((size_t)b * CIN + ci_base) * H_ + h) * W_ + w;
    #pragma unroll
    for (int i = 0; i < 20; i++) {
        int ci0 = i * 8 + cq * 2;          // 0..158, even
        float va = xb[(size_t)ci0 * H_ * W_];
        float vb = xb[(size_t)(ci0 + 1) * H_ * W_];
        float qa = fminf(fmaxf(rintf(va * inv) + zp, -128.f), 127.f) - zp;
        float qb = fminf(fmaxf(rintf(vb * inv) + zp, -128.f), 127.f) - zp;
        __half2 hq = __floats2half2_rn(qa, qb);
        t32[w * QSTR + (ci0 >> 1)] = *reinterpret_cast<uint32_t*>(&hq);
    }
    __syncthreads();

    // write out: 64 pixels x 80 words = 5120 words, coalesced
    uint32_t* gout = reinterpret_cast<uint32_t*>(
        g_xh + ((size_t)bh * W_) * CIN + ci_base);
    #pragma unroll
    for (int i = 0; i < 20; i++) {
        int idx = tid + i * 256;
        int ww  = idx / 80;
        int c   = idx - ww * 80;
        gout[(size_t)ww * (CIN / 2) + c] = t32[ww * QSTR + c];
    }
}

// ---------------- Main fp16 HMMA implicit-GEMM conv ----------------
static constexpr int A_STG = BM * 128;            // 40960
static constexpr int B_STG = BN * 128;            // 16384
static constexpr int STG   = A_STG + B_STG;       // 57344
static constexpr int SMEM_TOTAL = NSTG * STG;     // 172032

__global__ __launch_bounds__(NTH, 1)
void conv_hmma_kernel(const float* __restrict__ scale,
                      const float* __restrict__ bias,
                      float* __restrict__ out)
{
    extern __shared__ __align__(128) unsigned char sm[];
    const uint32_t smb = (uint32_t)__cvta_generic_to_shared(sm);

    const int tid  = threadIdx.x;
    const int warp = tid >> 5;             // 0..19
    const int lane = tid & 31;
    const int wm   = (warp >> 1) * 32;     // 0..288
    const int wn   = (warp & 1) * 64;      // 0/64

    const int n0 = blockIdx.x * BN;        // flat pixel base

    float acc[2][8][4];
    #pragma unroll
    for (int mt = 0; mt < 2; mt++)
        #pragma unroll
        for (int nt = 0; nt < 8; nt++)
            #pragma unroll
            for (int r = 0; r < 4; r++)
                acc[mt][nt][r] = 0.f;

    auto load_stage = [&](int it) {
        const int kb  = it * BK;
        const int tap = kb / 320;
        const int cib = kb - tap * 320;
        const int kh  = tap / 3;
        const int kw  = tap - kh * 3;
        const int dp  = (kh - 1) * W_ + (kw - 1);
        const uint32_t base = smb + (it % NSTG) * STG;
        // A: 320 rows x 128B (2560 x 16B)
        #pragma unroll
        for (int t = 0; t < 4; t++) {
            int idx = tid + t * NTH;
            int row = idx >> 3, vec = idx & 7;
            const void* src = g_wh + (size_t)row * KTOT + kb + vec * 8;
            cp_async16_cg(base + swz(row, vec * 16), src, 16);
        }
        // B: 128 n-rows x 128B (1024 x 16B); L1-cached (9x reuse across taps)
        #pragma unroll
        for (int t = 0; t < 2; t++) {
            int idx = tid + t * NTH;
            if (idx < 1024) {
                int row = idx >> 3, vec = idx & 7;
                int n   = n0 + row;
                int rem = n & 4095;
                int h   = rem >> 6, w = rem & 63;
                int ih  = h + kh - 1;
                int iw  = w + kw - 1;
                bool okb = ((unsigned)ih < (unsigned)H_) && ((unsigned)iw < (unsigned)W_);
                size_t p = okb ? (size_t)(n + dp) : 0;
                const void* src = g_xh + p * CIN + cib + vec * 8;
                cp_async16_ca(base + A_STG + swz(row, vec * 16), src, okb ? 16 : 0);
            }
        }
        asm volatile("cp.async.commit_group;\n" ::: "memory");
    };

    load_stage(0);
    load_stage(1);

    const uint32_t a_row = wm + (lane & 15);
    const uint32_t b_row = wn + (lane & 15);
    const uint32_t hi16  = (lane >> 4) * 16;

    for (int it = 0; it < NKI; it++) {
        if (it + 1 < NKI) asm volatile("cp.async.wait_group 1;\n" ::: "memory");
        else              asm volatile("cp.async.wait_group 0;\n" ::: "memory");
        __syncthreads();
        if (it + 2 < NKI) load_stage(it + 2);

        const uint32_t Ab = smb + (it % NSTG) * STG;
        const uint32_t Bb = Ab + A_STG;
        #pragma unroll
        for (int ks = 0; ks < 4; ks++) {
            uint32_t a[2][4];
            #pragma unroll
            for (int mt = 0; mt < 2; mt++)
                ldsm_x4(a[mt], Ab + swz(a_row + mt * 16, ks * 32 + hi16));
            #pragma unroll
            for (int p = 0; p < 4; p++) {
                uint32_t bf[4];
                ldsm_x4(bf, Bb + swz(b_row + p * 16, ks * 32 + hi16));
                #pragma unroll
                for (int mt = 0; mt < 2; mt++) {
                    hmma(acc[mt][p * 2 + 0], a[mt], bf[0], bf[2]);
                    hmma(acc[mt][p * 2 + 1], a[mt], bf[1], bf[3]);
                }
            }
        }
    }

    // ---------------- epilogue (direct fragment -> gmem, flat n) ----------------
    #pragma unroll
    for (int mt = 0; mt < 2; mt++) {
        const int o0 = wm + mt * 16 + (lane >> 2);
        const int o1 = o0 + 8;
        const float sc0 = scale[o0];
        const float sc1 = scale[o1];
        const float bb0 = bias[o0];
        const float bb1 = bias[o1];
        #pragma unroll
        for (int nt = 0; nt < 8; nt++) {
            const int n   = n0 + wn + nt * 8 + (lane & 3) * 2;
            const int b   = n >> 12;
            const int rem = n & 4095;
            float2 v0, v1;
            v0.x = sc0 * acc[mt][nt][0] + bb0;
            v0.y = sc0 * acc[mt][nt][1] + bb0;
            v1.x = sc1 * acc[mt][nt][2] + bb1;
            v1.y = sc1 * acc[mt][nt][3] + bb1;
            size_t p0 = ((size_t)b * COUT + o0) * 4096 + rem;
            size_t p1 = ((size_t)b * COUT + o1) * 4096 + rem;
            *reinterpret_cast<float2*>(out + p0) = v0;
            *reinterpret_cast<float2*>(out + p1) = v1;
        }
    }
}

// ---------------- Launch ----------------
// Inputs: 0:x f32  1:weight_int i32  2:weight_sum (unused)  3:scale f32
//         4:act_scales_inv f32  5:act_zero_points f32  6:bias f32 ; out f32
extern "C" void kernel_launch(void* const* d_in, const int* in_sizes, int n_in,
                              void* d_out, int out_size)
{
    const float* x    = (const float*)d_in[0];
    const int*   wint = (const int*)  d_in[1];
    const float* scl  = (const float*)d_in[3];
    const float* inv  = (const float*)d_in[4];
    const float* zp   = (const float*)d_in[5];
    const float* bias = (const float*)d_in[6];
    float* out = (float*)d_out;

    cudaFuncSetAttribute(conv_hmma_kernel,
                         cudaFuncAttributeMaxDynamicSharedMemorySize, SMEM_TOTAL);

    // fused prep: 1024 quant blocks + 320 weight blocks
    prep_kernel<<<1344, 256>>>(x, wint, inv, zp);
    // fp16 HMMA implicit GEMM
    conv_hmma_kernel<<<NPIX / BN, NTH, SMEM_TOTAL>>>(scl, bias, out);
}